// round 15
// baseline (speedup 1.0000x reference)
#include <cuda_runtime.h>
#include <cuda_bf16.h>
#include <math.h>
#include <stdint.h>

#define BATCHES   64
#define HEADS     8
#define HIDDEN    256
#define DTOT      2048
#define N_PAD     96
#define SCALE     0.08838834764831845f   // 1/sqrt(128)

// ---------------- device scratch ----------------
__device__ int   g_cnt[BATCHES];
__device__ int   g_start[BATCHES];
__device__ int   g_order[BATCHES];
__device__ float g_M2[HEADS * 128 * 128];   // M2[h][i][j] = (Wq_h @ Wk_h^T)[i][j]
__device__ float g_P[1024 * 128];           // P[(h*128+i)*128+j] = (Wv_h @ Wo_h)[i][j]
__device__ float g_u[HEADS][128];
__device__ float g_w2[HEADS][128];
__device__ float g_cc[HEADS];
__device__ float g_cout_part[16][128];

// ================= prep kernel =================
// bid 0..63    : M2 64x32 tiles      bid 64..127 : P 64x32 tiles
// bid 128      : counts + sort       bid 129     : cc
// bid 130..385 : u / w2              bid 386..393: cout partials
__global__ void k_prep(const int* __restrict__ batch,
                       const float* __restrict__ Wq, const float* __restrict__ bq,
                       const float* __restrict__ Wk, const float* __restrict__ bk,
                       const float* __restrict__ Wv, const float* __restrict__ bv,
                       const float* __restrict__ Wo, const float* __restrict__ bo,
                       int total) {
    int bid = blockIdx.x;
    int tid = threadIdx.x;

    if (bid < 128) {
        bool doP = (bid >= 64);
        int q = bid & 63;
        int h = q >> 3;
        int i0 = ((q >> 2) & 1) * 64;
        int j0 = (q & 3) * 32;
        int hoff = h * HIDDEN;
        __shared__ __align__(16) float As[32][68];   // [k][i]
        __shared__ __align__(16) float Bs[32][36];   // [k][j]
        const float* Abase = doP ? Wv : Wq;

        // A: two float4 per thread (64 rows x 8 float4)
        int fA0 = tid * 2, fA1 = tid * 2 + 1;
        int iiA0 = fA0 >> 3, t4A0 = fA0 & 7;
        int iiA1 = fA1 >> 3, t4A1 = fA1 & 7;
        // B: one float4 per thread
        int iiB = tid >> 3, t4B = tid & 7;       // M2: j-row 0..31, k-f4 0..7
        int kB  = tid >> 3, j4B = tid & 7;       // P : k-row 0..31, j-f4 0..7

        float4 a0r, a1r, b0r;
        a0r = *(const float4*)&Abase[(i0 + iiA0) * DTOT + hoff + t4A0 * 4];
        a1r = *(const float4*)&Abase[(i0 + iiA1) * DTOT + hoff + t4A1 * 4];
        if (!doP) b0r = *(const float4*)&Wk[(j0 + iiB) * DTOT + hoff + t4B * 4];
        else      b0r = *(const float4*)&Wo[(hoff + kB) * 128 + j0 + j4B * 4];

        int ty4 = (tid >> 4) * 4;     // i offset (4 rows)
        int tx2 = (tid & 15) * 2;     // j offset (2 cols)
        float acc[4][2] = {};
        for (int ch = 0; ch < 8; ch++) {
            __syncthreads();
            As[t4A0 * 4 + 0][iiA0] = a0r.x; As[t4A0 * 4 + 1][iiA0] = a0r.y;
            As[t4A0 * 4 + 2][iiA0] = a0r.z; As[t4A0 * 4 + 3][iiA0] = a0r.w;
            As[t4A1 * 4 + 0][iiA1] = a1r.x; As[t4A1 * 4 + 1][iiA1] = a1r.y;
            As[t4A1 * 4 + 2][iiA1] = a1r.z; As[t4A1 * 4 + 3][iiA1] = a1r.w;
            if (!doP) {
                Bs[t4B * 4 + 0][iiB] = b0r.x; Bs[t4B * 4 + 1][iiB] = b0r.y;
                Bs[t4B * 4 + 2][iiB] = b0r.z; Bs[t4B * 4 + 3][iiB] = b0r.w;
            } else {
                *(float4*)&Bs[kB][j4B * 4] = b0r;
            }
            __syncthreads();
            if (ch < 7) {
                int t0 = (ch + 1) * 32;
                a0r = *(const float4*)&Abase[(i0 + iiA0) * DTOT + hoff + t0 + t4A0 * 4];
                a1r = *(const float4*)&Abase[(i0 + iiA1) * DTOT + hoff + t0 + t4A1 * 4];
                if (!doP) b0r = *(const float4*)&Wk[(j0 + iiB) * DTOT + hoff + t0 + t4B * 4];
                else      b0r = *(const float4*)&Wo[(hoff + t0 + kB) * 128 + j0 + j4B * 4];
            }
#pragma unroll
            for (int t = 0; t < 32; t++) {
                float4 a4 = *(const float4*)&As[t][ty4];
                float2 b2 = *(const float2*)&Bs[t][tx2];
                float av[4] = {a4.x, a4.y, a4.z, a4.w};
#pragma unroll
                for (int u = 0; u < 4; u++) {
                    acc[u][0] = fmaf(av[u], b2.x, acc[u][0]);
                    acc[u][1] = fmaf(av[u], b2.y, acc[u][1]);
                }
            }
        }
        float* dst = doP ? g_P : g_M2;
#pragma unroll
        for (int u = 0; u < 4; u++) {
            *(float2*)&dst[(h * 128 + i0 + ty4 + u) * 128 + j0 + tx2] =
                make_float2(acc[u][0], acc[u][1]);
        }
        return;
    }
    if (bid == 128) {
        __shared__ int ends[BATCHES];
        __shared__ int cnt[BATCHES];
        for (int i = tid; i < total; i += 256) {
            int bcur = batch[i];
            int bnxt = (i + 1 < total) ? batch[i + 1] : -1;
            if (bcur != bnxt) ends[bcur] = i + 1;
        }
        __syncthreads();
        if (tid < BATCHES) {
            int e = ends[tid];
            int s = (tid > 0) ? ends[tid - 1] : 0;
            g_start[tid] = s;
            cnt[tid] = e - s;
            g_cnt[tid] = e - s;
        }
        __syncthreads();
        if (tid < BATCHES) {
            int myc = cnt[tid];
            int rank = 0;
#pragma unroll 8
            for (int b = 0; b < BATCHES; b++) {
                int cb = cnt[b];
                rank += (cb > myc) || (cb == myc && b < tid);
            }
            g_order[rank] = tid;
        }
        return;
    }
    if (bid == 129) {
        int h = tid >> 5, lane = tid & 31;
        float s = 0.f;
#pragma unroll
        for (int q = 0; q < 8; q++) {
            int k = h * HIDDEN + lane + 32 * q;
            s = fmaf(bq[k], bk[k], s);
        }
#pragma unroll
        for (int o = 16; o; o >>= 1) s += __shfl_xor_sync(0xffffffffu, s, o);
        if (lane == 0) g_cc[h] = s;
        return;
    }
    if (bid < 386) {
        int gw = (bid - 130) * 8 + (tid >> 5);
        int lane = tid & 31;
        int which = gw >> 10;
        int h = (gw >> 7) & 7, i = gw & 127;
        const float* W  = which ? Wk : Wq;
        const float* bb = which ? bq : bk;
        float s = 0.f;
#pragma unroll
        for (int q = 0; q < 8; q++) {
            int k = lane + 32 * q;
            s = fmaf(W[i * DTOT + h * HIDDEN + k], bb[h * HIDDEN + k], s);
        }
#pragma unroll
        for (int o = 16; o; o >>= 1) s += __shfl_xor_sync(0xffffffffu, s, o);
        if (lane == 0) {
            if (which) g_w2[h][i] = s; else g_u[h][i] = s;
        }
        return;
    }
    {
        int p = bid - 386;
        int j = tid & 127;
        int half = tid >> 7;
        int k0 = p * 256 + half * 128;
        float s = 0.f;
#pragma unroll 8
        for (int kk = 0; kk < 128; kk++) {
            int k = k0 + kk;
            s = fmaf(bv[k], Wo[k * 128 + j], s);
        }
        g_cout_part[p * 2 + half][j] = s;
    }
}

// ---- out init ----
__global__ void k_init(float* __restrict__ out, const float* __restrict__ bo) {
    int b = blockIdx.x, j = threadIdx.x;
    float s = bo[j];
#pragma unroll
    for (int q = 0; q < 16; q++) s += g_cout_part[q][j];
    out[b * 128 + j] = 96.0f * s;
}

__global__ void k_nop() {}

// ======= fused attention (tf32, permuted-X, A-prefetch depth 3) =======
#define XS 104
#define XT_FLOATS (128 * XS)
#define SMEM_FLOATS (2 * XT_FLOATS + 96 + 2*96 + 2*96 + 2*128 + 2*128 + 2*128)
#define SMEM_BYTES  (SMEM_FLOATS * 4)

__device__ __forceinline__ void mma_tf32(float c[4],
    uint32_t a0, uint32_t a1, uint32_t a2, uint32_t a3,
    uint32_t b0, uint32_t b1) {
    asm volatile(
        "mma.sync.aligned.m16n8k8.row.col.f32.tf32.tf32.f32 "
        "{%0,%1,%2,%3}, {%4,%5,%6,%7}, {%8,%9}, {%0,%1,%2,%3};\n"
        : "+f"(c[0]), "+f"(c[1]), "+f"(c[2]), "+f"(c[3])
        : "r"(a0), "r"(a1), "r"(a2), "r"(a3), "r"(b0), "r"(b1));
}

__device__ __forceinline__ void ld_brow(const float* __restrict__ row, float* b) {
    float4 v0 = ((const float4*)row)[0];
    float4 v1 = ((const float4*)row)[1];
    float4 v2 = ((const float4*)row)[2];
    b[0] = v0.x; b[1] = v0.y; b[2]  = v0.z; b[3]  = v0.w;
    b[4] = v1.x; b[5] = v1.y; b[6]  = v1.z; b[7]  = v1.w;
    b[8] = v2.x; b[9] = v2.y; b[10] = v2.z; b[11] = v2.w;
}

__device__ __forceinline__ void ld_afrag(const float* ap,
    uint32_t& x0, uint32_t& x1, uint32_t& x2, uint32_t& x3) {
    x0 = __float_as_uint(ap[0]);   x1 = __float_as_uint(ap[8]);
    x2 = __float_as_uint(ap[512]); x3 = __float_as_uint(ap[520]);
}

__global__ void __launch_bounds__(256, 2) k_attn(const float* __restrict__ X,
                                                 float* __restrict__ out) {
    int b = g_order[blockIdx.x];
    int h0 = blockIdx.y * 2;
    int c = g_cnt[b];
    int st = g_start[b];
    float pcount = (float)(N_PAD - c);
    extern __shared__ float sm[];
    float* Xt = sm;                        // permuted X^T: Xp[j][m'], m'=(m&7)*12+(m>>3)
    float* Tt = sm + XT_FLOATS;            // stage / T [j][n] / S [n][m]
    float* sw = sm + 2 * XT_FLOATS;
    float* qa = sw + 96;
    float* ka = qa + 192;
    float* us = ka + 192;
    float* ws = us + 256;
    float* zb = ws + 256;
    int tid = threadIdx.x;
    const int w = tid >> 5, lane = tid & 31;
    const int la = lane & 3, lb = lane >> 2;
    const int NT = (c + 7) >> 3;
    const int WS = (c + 15) >> 4;

    // ---- stage X f32 coalesced (stride 132) ----
    float4* stage4 = (float4*)Tt;
    for (int idx = tid; idx < c * 32; idx += 256) {
        int m = idx >> 5, l = idx & 31;
        stage4[m * 33 + l] = *(const float4*)&X[(st + m) * 128 + 4 * l];
    }
    if (tid < 128) { us[tid] = g_u[h0][tid];        ws[tid] = g_w2[h0][tid]; }
    else { us[tid] = g_u[h0 + 1][tid - 128];        ws[tid] = g_w2[h0 + 1][tid - 128]; }
    __syncthreads();

    // ---- bias terms for both heads ----
    if (tid < c) {
        const float4* xr = stage4 + tid * 33;
        const float4* u0 = (const float4*)us;
        const float4* u1 = (const float4*)(us + 128);
        const float4* w0 = (const float4*)ws;
        const float4* w1 = (const float4*)(ws + 128);
        float q0 = 0.f, k0 = 0.f, q1 = 0.f, k1 = 0.f;
#pragma unroll 4
        for (int j4 = 0; j4 < 32; j4++) {
            float4 xv = xr[j4];
            float4 a = u0[j4], bb = w0[j4], cc = u1[j4], dd = w1[j4];
            q0 = fmaf(xv.x, a.x, q0); k0 = fmaf(xv.x, bb.x, k0);
            q1 = fmaf(xv.x, cc.x, q1); k1 = fmaf(xv.x, dd.x, k1);
            q0 = fmaf(xv.y, a.y, q0); k0 = fmaf(xv.y, bb.y, k0);
            q1 = fmaf(xv.y, cc.y, q1); k1 = fmaf(xv.y, dd.y, k1);
            q0 = fmaf(xv.z, a.z, q0); k0 = fmaf(xv.z, bb.z, k0);
            q1 = fmaf(xv.z, cc.z, q1); k1 = fmaf(xv.z, dd.z, k1);
            q0 = fmaf(xv.w, a.w, q0); k0 = fmaf(xv.w, bb.w, k0);
            q1 = fmaf(xv.w, cc.w, q1); k1 = fmaf(xv.w, dd.w, k1);
        }
        qa[tid]       = SCALE * (q0 + g_cc[h0]);
        ka[tid]       = SCALE * k0;
        qa[96 + tid]  = SCALE * (q1 + g_cc[h0 + 1]);
        ka[96 + tid]  = SCALE * k1;
    }
    // ---- transpose stage -> Xp (permuted m', zero-pad m >= c) ----
    for (int idx = tid; idx < 128 * 96; idx += 256) {
        int j = idx / 96, m = idx - j * 96;
        int mp = (m & 7) * 12 + (m >> 3);
        Xt[j * XS + mp] = (m < c) ? Tt[m * 132 + j] : 0.f;
    }
    __syncthreads();

    for (int hh = 0; hh < 2; hh++) {
        const float* Mg = g_M2 + ((h0 + hh) << 14);
        const float* qah = qa + hh * 96;
        const float* kah = ka + hh * 96;
        const float* Abase = Mg + la * 128 + 16 * w + lb;

        // ---------- GEMM1: T[j][n] = sum_i M[i][j] X[n][i]  (A-prefetch depth 3) ----------
        {
            float c1[12][4];
#pragma unroll
            for (int r = 0; r < 12; r++) { c1[r][0] = 0; c1[r][1] = 0; c1[r][2] = 0; c1[r][3] = 0; }
            uint32_t a0, a1, a2, a3, n0r, n1r, n2r, n3r, p0, p1, p2, p3;
            ld_afrag(Abase,             a0, a1, a2, a3);
            ld_afrag(Abase + 8 * 128,   n0r, n1r, n2r, n3r);
            ld_afrag(Abase + 16 * 128,  p0, p1, p2, p3);
#pragma unroll
            for (int ks = 0; ks < 16; ks++) {
                uint32_t q0 = 0, q1 = 0, q2 = 0, q3 = 0;
                if (ks < 13) ld_afrag(Abase + (ks + 3) * 8 * 128, q0, q1, q2, q3);
                float b0v[12], b1v[12];
                ld_brow(Xt + (ks * 8 + la) * XS + 12 * lb, b0v);
                ld_brow(Xt + (ks * 8 + la + 4) * XS + 12 * lb, b1v);
#pragma unroll
                for (int nt = 0; nt < 12; nt++) {
                    if (nt < NT)
                        mma_tf32(c1[nt], a0, a1, a2, a3,
                                 __float_as_uint(b0v[nt]), __float_as_uint(b1v[nt]));
                }
                a0 = n0r; a1 = n1r; a2 = n2r; a3 = n3r;
                n0r = p0; n1r = p1; n2r = p2; n3r = p3;
                p0 = q0; p1 = q1; p2 = q2; p3 = q3;
            }
            if (hh == 1) __syncthreads();     // head 1: prior softmax/z done with Tt
            int r0 = 16 * w + lb;
#pragma unroll
            for (int nt = 0; nt < 12; nt++) {
                if (nt < NT) {
                    *(float2*)&Tt[r0 * XS + nt * 8 + 2 * la] = make_float2(c1[nt][0], c1[nt][1]);
                    *(float2*)&Tt[(r0 + 8) * XS + nt * 8 + 2 * la] = make_float2(c1[nt][2], c1[nt][3]);
                }
            }
        }
        __syncthreads();

        // ---------- GEMM2: S[n][m] = sum_j T[n][j] X[m][j]; warps < WS ----------
        float d[12][4];
#pragma unroll
        for (int r = 0; r < 12; r++) { d[r][0] = 0; d[r][1] = 0; d[r][2] = 0; d[r][3] = 0; }
        if (w < WS) {
#pragma unroll
            for (int ks = 0; ks < 16; ks++) {
                const float* tp = Tt + (ks * 8 + la) * XS + 16 * w + lb;
                uint32_t a0 = __float_as_uint(tp[0]);
                uint32_t a1 = __float_as_uint(tp[8]);
                uint32_t a2 = __float_as_uint(tp[4 * XS]);
                uint32_t a3 = __float_as_uint(tp[4 * XS + 8]);
                float b0v[12], b1v[12];
                ld_brow(Xt + (ks * 8 + la) * XS + 12 * lb, b0v);
                ld_brow(Xt + (ks * 8 + la + 4) * XS + 12 * lb, b1v);
#pragma unroll
                for (int mt = 0; mt < 12; mt++) {
                    if (mt < NT)
                        mma_tf32(d[mt], a0, a1, a2, a3,
                                 __float_as_uint(b0v[mt]), __float_as_uint(b1v[mt]));
                }
            }
        }
        __syncthreads();                      // Tt reads done before S overwrite
        float* Ss = Tt;                       // Ss[n][m], stride XS
        if (w < WS) {
            int nr = 16 * w + lb;
#pragma unroll
            for (int mt = 0; mt < 12; mt++) {
                if (mt < NT) {
                    int mb = mt * 8 + 2 * la;
                    Ss[(nr    ) * XS + mb    ] = d[mt][0];
                    Ss[(nr    ) * XS + mb + 1] = d[mt][1];
                    Ss[(nr + 8) * XS + mb    ] = d[mt][2];
                    Ss[(nr + 8) * XS + mb + 1] = d[mt][3];
                }
            }
        }
        if (tid < 96) sw[tid] = (tid < c) ? pcount * (1.0f / 96.0f) : 0.f;
        __syncthreads();

        // ---------- fused softmax + key-mass ----------
        const int m0 = lane, m1 = lane + 32, m2 = lane + 64;
        const bool v0 = m0 < c, v1 = m1 < c, v2 = m2 < c;
        const float ka0 = v0 ? kah[m0] : 0.f;
        const float ka1 = v1 ? kah[m1] : 0.f;
        const float ka2 = v2 ? kah[m2] : 0.f;
        float aW0 = 0.f, aW1 = 0.f, aW2 = 0.f;
#pragma unroll
        for (int k = 0; k < 12; k++) {
            int n = w + 8 * k;
            if (n < c) {
                float qan = qah[n];
                const float* Sr = Ss + n * XS;
                float e0 = v0 ? __expf(fmaf(SCALE, Sr[m0], qan + ka0)) : 0.f;
                float e1 = v1 ? __expf(fmaf(SCALE, Sr[m1], qan + ka1)) : 0.f;
                float e2 = v2 ? __expf(fmaf(SCALE, Sr[m2], qan + ka2)) : 0.f;
                float se = e0 + e1 + e2;
#pragma unroll
                for (int o = 16; o; o >>= 1) se += __shfl_xor_sync(0xffffffffu, se, o);
                se += pcount * __expf(qan);
                float iv = __fdividef(1.0f, se);
                aW0 = fmaf(e0, iv, aW0);
                aW1 = fmaf(e1, iv, aW1);
                aW2 = fmaf(e2, iv, aW2);
            }
        }
        if (v0) atomicAdd(&sw[m0], aW0);
        if (v1) atomicAdd(&sw[m1], aW1);
        if (v2) atomicAdd(&sw[m2], aW2);
        __syncthreads();

        // ---------- z[i] = sum_m sw[m] * x_m[i]  (permuted column read) ----------
        {
            bool u1v = lane + 32 < c, u2v = lane + 64 < c;
            float s0 = (lane < c) ? sw[lane] : 0.f;
            float s1 = u1v ? sw[lane + 32] : 0.f;
            float s2 = u2v ? sw[lane + 64] : 0.f;
            int mp0 = (lane & 7) * 12 + (lane >> 3);
#pragma unroll
            for (int q = 0; q < 16; q++) {
                int i = w + 8 * q;
                const float* Xr = Xt + i * XS;
                float part = s0 * Xr[mp0];
                part = fmaf(s1, Xr[mp0 + 4], part);
                part = fmaf(s2, Xr[mp0 + 8], part);
#pragma unroll
                for (int o = 16; o; o >>= 1) part += __shfl_xor_sync(0xffffffffu, part, o);
                if (lane == 0) zb[hh * 128 + i] = part;
            }
        }
        __syncthreads();
    }

    // ---------- fused output ----------
    {
        int half = tid >> 7, j = tid & 127;
        const float* Pp = g_P + ((h0 + half) << 14) + j;
        const float* zp = zb + half * 128;
        float a0 = 0.f, a1 = 0.f, a2 = 0.f, a3 = 0.f;
#pragma unroll
        for (int i = 0; i < 128; i += 4) {
            a0 = fmaf(zp[i    ], Pp[(i    ) * 128], a0);
            a1 = fmaf(zp[i + 1], Pp[(i + 1) * 128], a1);
            a2 = fmaf(zp[i + 2], Pp[(i + 2) * 128], a2);
            a3 = fmaf(zp[i + 3], Pp[(i + 3) * 128], a3);
        }
        atomicAdd(&out[b * 128 + j], (a0 + a1) + (a2 + a3));
    }
}

// ================= launch =================
extern "C" void kernel_launch(void* const* d_in, const int* in_sizes, int n_in,
                              void* d_out, int out_size) {
    const float* x     = (const float*)d_in[0];
    const int*   batch = (const int*)  d_in[1];
    const float* Wq    = (const float*)d_in[2];
    const float* bq    = (const float*)d_in[3];
    const float* Wk    = (const float*)d_in[4];
    const float* bk    = (const float*)d_in[5];
    const float* Wv    = (const float*)d_in[6];
    const float* bv    = (const float*)d_in[7];
    const float* Wo    = (const float*)d_in[8];
    const float* bo    = (const float*)d_in[9];
    float* out = (float*)d_out;
    int total = in_sizes[1];

    cudaFuncSetAttribute(k_attn, cudaFuncAttributeMaxDynamicSharedMemorySize, SMEM_BYTES);

    k_prep<<<394, 256>>>(batch, Wq, bq, Wk, bk, Wv, bv, Wo, bo, total);
    k_init<<<BATCHES, 128>>>(out, bo);
    k_nop<<<1, 32>>>();
    k_attn<<<dim3(BATCHES, 4), 256, SMEM_BYTES>>>(x, out);
}